// round 11
// baseline (speedup 1.0000x reference)
#include <cuda_runtime.h>
#include <math.h>

// ---------------- problem constants (fixed shapes from setup_inputs) -------
#define NB      32          // batch
#define TSAMP   160000      // samples per batch
#define KFFT    1024        // n_fft
#define MWIN    800         // win_length
#define HOP     600
#define NBINS   256
#define NF      267         // 1 + (160000+1024-1024)/600
#define NFP     134         // frame pairs (two real frames per complex FFT)
#define NFQ     67          // frame-pair pairs (two FFTs per block)
#define LMAXW   13
#define LMINW   3
#define FT      (NBINS*NF)  // 68352 (worst-case valid keys per batch)

#define PHI1(a) ((a) + 4 * ((a) >> 4))   // skew for stage1->stage2 buffer
#define TWI(i)  ((i) + ((i) >> 4))       // skewed twiddle index (CF strided reads)

__device__ __forceinline__ float2 cmul(float2 a, float2 b) {
    return make_float2(a.x * b.x - a.y * b.y, a.x * b.y + a.y * b.x);
}

// ---------------- scratch (__device__ globals, no allocation) --------------
__device__ float        g_Y[NB*NBINS*NF];       // [B, F, T]
__device__ unsigned int g_keys[NB*FT];          // compacted valid keys
__device__ int          g_nvalid[NB];
__device__ int          g_done;

// ---------------- STFT power: one block per (batch, 2 frame-pairs) ---------
// Four real frames per block: two complex 1024-pt FFTs (radix-4 Stockham,
// two reals packed per FFT). Twiddle table + Hann window built once per
// block; input register-resident through stage 0; trimmed final stage.
__global__ __launch_bounds__(256) void stft_kernel(const float* __restrict__ y) {
    const int q = blockIdx.x % NFQ;
    const int b = blockIdx.x / NFQ;
    __shared__ __align__(16) float2 A[1280];
    __shared__ __align__(16) float2 B[1024];
    __shared__ float2 stw[272];
    __shared__ float  win[MWIN];
    const int tid = threadIdx.x;

    if (q == 0 && tid == 0) g_nvalid[b] = 0;     // replay-state reset

    {   // twiddle table: exp(-2*pi*i*k/1024), k<256, skew-stored
        float s, c;
        sincospif(-(float)tid / 512.0f, &s, &c);
        stw[TWI(tid)] = make_float2(c, s);
    }
    for (int i = tid; i < MWIN; i += 256)        // periodic hann
        win[i] = 0.5f - 0.5f * cospif((float)i / 400.0f);
    __syncthreads();

    const float* yb = y + (size_t)b * TSAMP;

    #define BFLY(w1, v0, v1, v2, v3, o0, o1, o2, o3)                          \
        {                                                                     \
            float2 w2 = cmul(w1, w1), w3 = cmul(w1, w2);                      \
            float2 a1 = cmul(w1, v1), a2 = cmul(w2, v2), a3 = cmul(w3, v3);   \
            float2 t0 = {v0.x + a2.x, v0.y + a2.y};                           \
            float2 t1 = {v0.x - a2.x, v0.y - a2.y};                           \
            float2 t2 = {a1.x + a3.x, a1.y + a3.y};                           \
            float2 t3 = {a1.x - a3.x, a1.y - a3.y};                           \
            o0 = make_float2(t0.x + t2.x, t0.y + t2.y);                       \
            o1 = make_float2(t1.x + t3.y, t1.y - t3.x);                       \
            o2 = make_float2(t0.x - t2.x, t0.y - t2.y);                       \
            o3 = make_float2(t1.x - t3.y, t1.y + t3.x);                       \
        }

    #pragma unroll
    for (int e = 0; e < 2; e++) {
        const int p  = 2 * q + e;
        const int fa = 2 * p;
        const int fb = 2 * p + 1;                // may be NF (dropped)

        // windowed input, elements tid+256k in registers (natural order)
        float2 v[4];
        #pragma unroll
        for (int k = 0; k < 4; k++) {
            int j = tid + k * 256;
            float va = 0.0f, vb = 0.0f;
            if (j >= 112 && j < 912) {           // zero-padded centered window
                float w = win[j - 112];
                int sa = fa * HOP + j - 512;     // center=True: pad K/2 = 512
                if (sa < 0) sa = -sa;
                else if (sa >= TSAMP) sa = 2 * (TSAMP - 1) - sa;
                va = __ldg(yb + sa) * w;
                if (fb < NF) {
                    int sb = fb * HOP + j - 512;
                    if (sb < 0) sb = -sb;
                    else if (sb >= TSAMP) sb = 2 * (TSAMP - 1) - sb;
                    vb = __ldg(yb + sb) * w;
                }
            }
            v[k] = make_float2(va, vb);
        }

        // stage 0 (Ns=1): registers -> B, contiguous STS.128 x2
        {
            float2 t0 = {v[0].x + v[2].x, v[0].y + v[2].y};
            float2 t1 = {v[0].x - v[2].x, v[0].y - v[2].y};
            float2 t2 = {v[1].x + v[3].x, v[1].y + v[3].y};
            float2 t3 = {v[1].x - v[3].x, v[1].y - v[3].y};
            ((float4*)B)[2 * tid]     = make_float4(t0.x + t2.x, t0.y + t2.y,
                                                    t1.x + t3.y, t1.y - t3.x);
            ((float4*)B)[2 * tid + 1] = make_float4(t0.x - t2.x, t0.y - t2.y,
                                                    t1.x - t3.y, t1.y + t3.x);
        }
        __syncthreads();

        // stage 1 (Ns=4): B -> A (PHI1 layout)
        {
            const int m = tid & 3;
            float2 v0 = B[tid], v1 = B[tid + 256], v2 = B[tid + 512], v3 = B[tid + 768];
            float2 w1 = stw[TWI(m * 64)];
            float2 o0, o1, o2, o3;
            BFLY(w1, v0, v1, v2, v3, o0, o1, o2, o3);
            const int base = ((tid >> 2) << 4) + m;
            A[PHI1(base)]      = o0; A[PHI1(base + 4)]  = o1;
            A[PHI1(base + 8)]  = o2; A[PHI1(base + 12)] = o3;
        }
        __syncthreads();

        // stage 2 (Ns=16): A (PHI1) -> B (identity)
        {
            const int m = tid & 15;
            float2 v0 = A[PHI1(tid)],       v1 = A[PHI1(tid + 256)];
            float2 v2 = A[PHI1(tid + 512)], v3 = A[PHI1(tid + 768)];
            float2 w1 = stw[TWI(m * 16)];
            float2 o0, o1, o2, o3;
            BFLY(w1, v0, v1, v2, v3, o0, o1, o2, o3);
            const int base = ((tid >> 4) << 6) + m;
            B[base]      = o0; B[base + 16] = o1;
            B[base + 32] = o2; B[base + 48] = o3;
        }
        __syncthreads();

        // stage 3 (Ns=64): B -> A (identity)
        {
            const int m = tid & 63;
            float2 v0 = B[tid], v1 = B[tid + 256], v2 = B[tid + 512], v3 = B[tid + 768];
            float2 w1 = stw[TWI(m * 4)];
            float2 o0, o1, o2, o3;
            BFLY(w1, v0, v1, v2, v3, o0, o1, o2, o3);
            const int base = ((tid >> 6) << 8) + m;
            A[base]       = o0; A[base + 64]  = o1;
            A[base + 128] = o2; A[base + 192] = o3;
        }
        __syncthreads();

        // stage 4 (Ns=256, trimmed): Z[tid] in regs; only Z[tid+768] -> smem
        float2 zk;
        {
            float2 v0 = A[tid], v1 = A[tid + 256], v2 = A[tid + 512], v3 = A[tid + 768];
            float2 w1 = stw[TWI(tid)];
            float2 w2 = cmul(w1, w1), w3 = cmul(w1, w2);
            float2 a1 = cmul(w1, v1), a2 = cmul(w2, v2), a3 = cmul(w3, v3);
            float2 t0 = {v0.x + a2.x, v0.y + a2.y};
            float2 t1 = {v0.x - a2.x, v0.y - a2.y};
            float2 t2 = {a1.x + a3.x, a1.y + a3.y};
            float2 t3 = {a1.x - a3.x, a1.y - a3.y};
            zk = make_float2(t0.x + t2.x, t0.y + t2.y);          // Z[tid]
            B[768 + tid] = make_float2(t1.x - t3.y, t1.y + t3.x); // Z[tid+768]
        }
        __syncthreads();

        // Hermitian unpack; power, layout [B, F, T]
        float2 zc = (tid == 0) ? zk : B[1024 - tid];  // Z[K - tid]
        float xar = 0.5f * (zk.x + zc.x), xai = 0.5f * (zk.y - zc.y);
        float ddr = zk.x - zc.x,          ddi = zk.y + zc.y;
        float xbr = 0.5f * ddi,           xbi = -0.5f * ddr;
        float* Yrow = g_Y + ((size_t)b * NBINS + tid) * NF;
        Yrow[fa] = xar * xar + xai * xai;
        if (fb < NF) Yrow[fb] = xbr * xbr + xbi * xbi;
        __syncthreads();                          // B reused next iteration
    }
}

// ---------------- RT60 + fused median (last-block) ---------------------------
__global__ __launch_bounds__(128) void rt60_kernel(const float* __restrict__ coeffs,
                                                   float* __restrict__ out) {
    const int f = blockIdx.x % NBINS;
    const int b = blockIdx.x / NBINS;
    __shared__ float        sy[NF];
    __shared__ unsigned int W[12];               // decrease-flag bitmask (267 bits)
    __shared__ unsigned int skey[NF];
    __shared__ int          sbest;
    __shared__ int          scnt;
    __shared__ int          sbase;
    __shared__ int          slast;
    __shared__ int          hist4[4][256];
    const int tid  = threadIdx.x;
    const int lane = tid & 31;
    if (tid < 12) W[tid] = 0u;
    if (tid == 0) { sbest = 0; scnt = 0; }

    const float* row = g_Y + ((size_t)b * NBINS + f) * NF;
    for (int t = tid; t < NF; t += 128) sy[t] = row[t];
    __syncthreads();

    // pack strict-decrease flags into bitmask words via ballot
    #pragma unroll
    for (int base = 0; base < 288; base += 128) {
        int t = base + tid;
        bool flag = (t + 1 < NF) && (sy[t + 1] < sy[t]);
        unsigned int m = __ballot_sync(0xFFFFFFFFu, flag);
        if (lane == 0 && (t >> 5) < 9) W[t >> 5] = m;
    }
    __syncthreads();

    // best window length: run length from t = ffs of first zero bit
    int localbest = 0;
    for (int t = tid; t < NF; t += 128) {
        int w = t >> 5, r = t & 31;
        unsigned int bits = (W[w] >> r) | (r ? (W[w + 1] << (32 - r)) : 0u);
        unsigned int nb = ~bits;
        int c = nb ? (__ffs(nb) - 1) : 32;
        if (c > LMAXW - 1) c = LMAXW - 1;
        int cand = c + 1;
        int rem  = NF - t;
        if (cand > rem) cand = rem;
        if (cand > localbest) localbest = cand;
    }
    atomicMax(&sbest, localbest);
    __syncthreads();

    const int lenL = sbest;                      // block-uniform
    if (lenL >= LMINW) {                         // uniform branch: syncs legal
        const float xm  = 0.5f * (float)(lenL - 1);
        const float den = (float)lenL * (float)(lenL * lenL - 1) / 12.0f;

        for (int t = tid; t < NF; t += 128) {
            int w = t >> 5, r = t & 31;
            unsigned int bits = (W[w] >> r) | (r ? (W[w + 1] << (32 - r)) : 0u);
            unsigned int nb = ~bits;
            int c = nb ? (__ffs(nb) - 1) : 32;
            if (t + lenL <= NF && c >= lenL - 1) {
                float acc = 0.0f;
                float db[LMAXW];
                for (int j = lenL - 1; j >= 0; j--) {
                    acc += sy[t + j];
                    db[j] = 10.0f * log10f(fmaxf(acc, 1e-10f));
                }
                float d0 = db[0];
                if (db[lenL - 1] - d0 < -10.0f) {
                    float num = 0.0f;
                    for (int j = 1; j < lenL; j++)
                        num += ((float)j - xm) * (db[j] - d0);
                    float slope = num / den;
                    float rt60  = (-60.0f / slope) * 0.0375f;  // HOP/FS
                    unsigned int u = __float_as_uint(rt60);
                    unsigned int key = (u & 0x80000000u) ? ~u : (u | 0x80000000u);
                    int pos = atomicAdd(&scnt, 1);
                    skey[pos] = key;
                }
            }
        }
        __syncthreads();
        const int cnt = scnt;
        if (cnt > 0) {
            if (tid == 0) sbase = atomicAdd(&g_nvalid[b], cnt);
            __syncthreads();
            unsigned int* dst = g_keys + (size_t)b * FT + sbase;
            for (int i = tid; i < cnt; i += 128) dst[i] = skey[i];
        }
    }

    // ---- last-block: median + polynomial correction for all batches ----
    __threadfence();
    if (tid == 0) {
        int t = atomicAdd(&g_done, 1);
        slast = (t == (int)gridDim.x - 1);
    }
    __syncthreads();
    if (!slast) return;
    __threadfence();

    const int w = tid >> 5;
    const float c0 = coeffs[0], c1 = coeffs[1];
    int* h = hist4[w];
    for (int i = 0; i < 8; i++) {                // warp handles 8 batches
        const int b2 = w * 8 + i;
        const int n = g_nvalid[b2];
        if (n == 0) {
            if (lane == 0) out[b2] = 0.5f;       // DEFAULT_RT60 (>= 0.01)
            continue;
        }
        const unsigned int* gk = g_keys + (size_t)b2 * FT;
        unsigned int pfx = 0u;
        int k0 = (n - 1) >> 1;
        #pragma unroll
        for (int pass = 0; pass < 4; pass++) {
            const int base = lane * 8;
            #pragma unroll
            for (int qq = 0; qq < 8; qq++) h[base + qq] = 0;
            __syncwarp();
            const int shift = 24 - 8 * pass;
            const unsigned int hmask = pass ? (0xFFFFFFFFu << (shift + 8)) : 0u;
            for (int ii = lane; ii < n; ii += 32) {
                unsigned int key = gk[ii];
                if ((key & hmask) == pfx) atomicAdd(&h[(key >> shift) & 255], 1);
            }
            __syncwarp();
            int c[8]; int s = 0;
            #pragma unroll
            for (int qq = 0; qq < 8; qq++) { c[qq] = h[base + qq]; s += c[qq]; }
            int excl = s;
            #pragma unroll
            for (int off = 1; off < 32; off <<= 1) {
                int nn = __shfl_up_sync(0xFFFFFFFFu, excl, off);
                if (lane >= off) excl += nn;
            }
            excl -= s;                            // exclusive prefix
            int bin = 256, cumAt = 0, cum = excl;
            #pragma unroll
            for (int qq = 0; qq < 8; qq++) {
                if (bin == 256 && cum + c[qq] > k0) { bin = base + qq; cumAt = cum; }
                cum += c[qq];
            }
            unsigned int ball = __ballot_sync(0xFFFFFFFFu, bin < 256);
            int src = __ffs(ball) - 1;            // guaranteed: total >= k0+1
            k0  = __shfl_sync(0xFFFFFFFFu, k0 - cumAt, src);
            pfx = __shfl_sync(0xFFFFFFFFu,
                              pfx | ((unsigned int)bin << shift), src);
            __syncwarp();
        }
        if (lane == 0) {
            unsigned int u = (pfx & 0x80000000u) ? (pfx ^ 0x80000000u) : ~pfx;
            float med = __uint_as_float(u);
            out[b2] = fmaxf(c0 + c1 * med, 0.01f);
        }
    }
    __syncthreads();
    if (tid == 0) g_done = 0;                    // reset for next graph replay
}

// ---------------- launcher ---------------------------------------------------
extern "C" void kernel_launch(void* const* d_in, const int* in_sizes, int n_in,
                              void* d_out, int out_size) {
    const float* y      = (const float*)d_in[0];
    const float* coeffs = (const float*)d_in[1];
    float*       out    = (float*)d_out;

    stft_kernel<<<NB * NFQ, 256>>>(y);
    rt60_kernel<<<NB * NBINS, 128>>>(coeffs, out);
}

// round 12
// speedup vs baseline: 1.7993x; 1.7993x over previous
#include <cuda_runtime.h>
#include <math.h>

// ---------------- problem constants (fixed shapes from setup_inputs) -------
#define NB      32          // batch
#define TSAMP   160000      // samples per batch
#define KFFT    1024        // n_fft
#define MWIN    800         // win_length
#define HOP     600
#define NBINS   256
#define NF      267         // 1 + (160000+1024-1024)/600
#define NFP     134         // frame pairs (two real frames per complex FFT)
#define NFQ     67          // frame-pair pairs (two FFTs per block)
#define LMAXW   13
#define LMINW   3
#define FT      (NBINS*NF)  // 68352 (worst-case valid keys per batch)
#define SMEMK   8192        // median smem key cache capacity

#define PHI1(a) ((a) + 4 * ((a) >> 4))   // skew for stage1->stage2 buffer
#define TWI(i)  ((i) + ((i) >> 4))       // skewed twiddle index (CF strided reads)

__device__ __forceinline__ float2 cmul(float2 a, float2 b) {
    return make_float2(a.x * b.x - a.y * b.y, a.x * b.y + a.y * b.x);
}

// ---------------- scratch (__device__ globals, no allocation) --------------
__device__ float        g_Y[NB*NBINS*NF];       // [B, F, T]
__device__ unsigned int g_keys[NB*FT];          // compacted valid keys
__device__ int          g_nvalid[NB];

// ---------------- STFT power: one block per (batch, 2 frame-pairs) ---------
// Four real frames per block: two complex 1024-pt FFTs (radix-4 Stockham,
// two reals packed per FFT). Twiddle table + Hann window built once per
// block; input register-resident through stage 0; trimmed final stage.
__global__ __launch_bounds__(256) void stft_kernel(const float* __restrict__ y) {
    const int q = blockIdx.x % NFQ;
    const int b = blockIdx.x / NFQ;
    __shared__ __align__(16) float2 A[1280];
    __shared__ __align__(16) float2 B[1024];
    __shared__ float2 stw[272];
    __shared__ float  win[MWIN];
    const int tid = threadIdx.x;

    if (q == 0 && tid == 0) g_nvalid[b] = 0;     // replay-state reset

    {   // twiddle table: exp(-2*pi*i*k/1024), k<256, skew-stored
        float s, c;
        sincospif(-(float)tid / 512.0f, &s, &c);
        stw[TWI(tid)] = make_float2(c, s);
    }
    for (int i = tid; i < MWIN; i += 256)        // periodic hann
        win[i] = 0.5f - 0.5f * cospif((float)i / 400.0f);
    __syncthreads();

    const float* yb = y + (size_t)b * TSAMP;

    #define BFLY(w1, v0, v1, v2, v3, o0, o1, o2, o3)                          \
        {                                                                     \
            float2 w2 = cmul(w1, w1), w3 = cmul(w1, w2);                      \
            float2 a1 = cmul(w1, v1), a2 = cmul(w2, v2), a3 = cmul(w3, v3);   \
            float2 t0 = {v0.x + a2.x, v0.y + a2.y};                           \
            float2 t1 = {v0.x - a2.x, v0.y - a2.y};                           \
            float2 t2 = {a1.x + a3.x, a1.y + a3.y};                           \
            float2 t3 = {a1.x - a3.x, a1.y - a3.y};                           \
            o0 = make_float2(t0.x + t2.x, t0.y + t2.y);                       \
            o1 = make_float2(t1.x + t3.y, t1.y - t3.x);                       \
            o2 = make_float2(t0.x - t2.x, t0.y - t2.y);                       \
            o3 = make_float2(t1.x - t3.y, t1.y + t3.x);                       \
        }

    #pragma unroll
    for (int e = 0; e < 2; e++) {
        const int p  = 2 * q + e;
        const int fa = 2 * p;
        const int fb = 2 * p + 1;                // may be NF (dropped)

        // windowed input, elements tid+256k in registers (natural order)
        float2 v[4];
        #pragma unroll
        for (int k = 0; k < 4; k++) {
            int j = tid + k * 256;
            float va = 0.0f, vb = 0.0f;
            if (j >= 112 && j < 912) {           // zero-padded centered window
                float w = win[j - 112];
                int sa = fa * HOP + j - 512;     // center=True: pad K/2 = 512
                if (sa < 0) sa = -sa;
                else if (sa >= TSAMP) sa = 2 * (TSAMP - 1) - sa;
                va = __ldg(yb + sa) * w;
                if (fb < NF) {
                    int sb = fb * HOP + j - 512;
                    if (sb < 0) sb = -sb;
                    else if (sb >= TSAMP) sb = 2 * (TSAMP - 1) - sb;
                    vb = __ldg(yb + sb) * w;
                }
            }
            v[k] = make_float2(va, vb);
        }

        // stage 0 (Ns=1): registers -> B, contiguous STS.128 x2
        {
            float2 t0 = {v[0].x + v[2].x, v[0].y + v[2].y};
            float2 t1 = {v[0].x - v[2].x, v[0].y - v[2].y};
            float2 t2 = {v[1].x + v[3].x, v[1].y + v[3].y};
            float2 t3 = {v[1].x - v[3].x, v[1].y - v[3].y};
            ((float4*)B)[2 * tid]     = make_float4(t0.x + t2.x, t0.y + t2.y,
                                                    t1.x + t3.y, t1.y - t3.x);
            ((float4*)B)[2 * tid + 1] = make_float4(t0.x - t2.x, t0.y - t2.y,
                                                    t1.x - t3.y, t1.y + t3.x);
        }
        __syncthreads();

        // stage 1 (Ns=4): B -> A (PHI1 layout)
        {
            const int m = tid & 3;
            float2 v0 = B[tid], v1 = B[tid + 256], v2 = B[tid + 512], v3 = B[tid + 768];
            float2 w1 = stw[TWI(m * 64)];
            float2 o0, o1, o2, o3;
            BFLY(w1, v0, v1, v2, v3, o0, o1, o2, o3);
            const int base = ((tid >> 2) << 4) + m;
            A[PHI1(base)]      = o0; A[PHI1(base + 4)]  = o1;
            A[PHI1(base + 8)]  = o2; A[PHI1(base + 12)] = o3;
        }
        __syncthreads();

        // stage 2 (Ns=16): A (PHI1) -> B (identity)
        {
            const int m = tid & 15;
            float2 v0 = A[PHI1(tid)],       v1 = A[PHI1(tid + 256)];
            float2 v2 = A[PHI1(tid + 512)], v3 = A[PHI1(tid + 768)];
            float2 w1 = stw[TWI(m * 16)];
            float2 o0, o1, o2, o3;
            BFLY(w1, v0, v1, v2, v3, o0, o1, o2, o3);
            const int base = ((tid >> 4) << 6) + m;
            B[base]      = o0; B[base + 16] = o1;
            B[base + 32] = o2; B[base + 48] = o3;
        }
        __syncthreads();

        // stage 3 (Ns=64): B -> A (identity)
        {
            const int m = tid & 63;
            float2 v0 = B[tid], v1 = B[tid + 256], v2 = B[tid + 512], v3 = B[tid + 768];
            float2 w1 = stw[TWI(m * 4)];
            float2 o0, o1, o2, o3;
            BFLY(w1, v0, v1, v2, v3, o0, o1, o2, o3);
            const int base = ((tid >> 6) << 8) + m;
            A[base]       = o0; A[base + 64]  = o1;
            A[base + 128] = o2; A[base + 192] = o3;
        }
        __syncthreads();

        // stage 4 (Ns=256, trimmed): Z[tid] in regs; only Z[tid+768] -> smem
        float2 zk;
        {
            float2 v0 = A[tid], v1 = A[tid + 256], v2 = A[tid + 512], v3 = A[tid + 768];
            float2 w1 = stw[TWI(tid)];
            float2 w2 = cmul(w1, w1), w3 = cmul(w1, w2);
            float2 a1 = cmul(w1, v1), a2 = cmul(w2, v2), a3 = cmul(w3, v3);
            float2 t0 = {v0.x + a2.x, v0.y + a2.y};
            float2 t1 = {v0.x - a2.x, v0.y - a2.y};
            float2 t2 = {a1.x + a3.x, a1.y + a3.y};
            float2 t3 = {a1.x - a3.x, a1.y - a3.y};
            zk = make_float2(t0.x + t2.x, t0.y + t2.y);          // Z[tid]
            B[768 + tid] = make_float2(t1.x - t3.y, t1.y + t3.x); // Z[tid+768]
        }
        __syncthreads();

        // Hermitian unpack; power, layout [B, F, T]
        float2 zc = (tid == 0) ? zk : B[1024 - tid];  // Z[K - tid]
        float xar = 0.5f * (zk.x + zc.x), xai = 0.5f * (zk.y - zc.y);
        float ddr = zk.x - zc.x,          ddi = zk.y + zc.y;
        float xbr = 0.5f * ddi,           xbi = -0.5f * ddr;
        float* Yrow = g_Y + ((size_t)b * NBINS + tid) * NF;
        Yrow[fa] = xar * xar + xai * xai;
        if (fb < NF) Yrow[fb] = xbr * xbr + xbi * xbi;
        __syncthreads();                          // B reused next iteration
    }
}

// ---------------- RT60 per (batch, subband): compact valid keys -------------
__global__ __launch_bounds__(128) void rt60_kernel() {
    const int f = blockIdx.x % NBINS;
    const int b = blockIdx.x / NBINS;
    __shared__ float        sy[NF];
    __shared__ unsigned int W[12];               // decrease-flag bitmask (267 bits)
    __shared__ unsigned int skey[NF];
    __shared__ int          sbest;
    __shared__ int          scnt;
    __shared__ int          sbase;
    const int tid  = threadIdx.x;
    const int lane = tid & 31;
    if (tid < 12) W[tid] = 0u;
    if (tid == 0) { sbest = 0; scnt = 0; }

    const float* row = g_Y + ((size_t)b * NBINS + f) * NF;
    for (int t = tid; t < NF; t += 128) sy[t] = row[t];
    __syncthreads();

    // pack strict-decrease flags into bitmask words via ballot
    #pragma unroll
    for (int base = 0; base < 288; base += 128) {
        int t = base + tid;
        bool flag = (t + 1 < NF) && (sy[t + 1] < sy[t]);
        unsigned int m = __ballot_sync(0xFFFFFFFFu, flag);
        if (lane == 0 && (t >> 5) < 9) W[t >> 5] = m;
    }
    __syncthreads();

    // best window length: run length from t = ffs of first zero bit
    int localbest = 0;
    for (int t = tid; t < NF; t += 128) {
        int w = t >> 5, r = t & 31;
        unsigned int bits = (W[w] >> r) | (r ? (W[w + 1] << (32 - r)) : 0u);
        unsigned int nb = ~bits;
        int c = nb ? (__ffs(nb) - 1) : 32;
        if (c > LMAXW - 1) c = LMAXW - 1;
        int cand = c + 1;
        int rem  = NF - t;
        if (cand > rem) cand = rem;
        if (cand > localbest) localbest = cand;
    }
    atomicMax(&sbest, localbest);
    __syncthreads();

    const int lenL = sbest;
    if (lenL < LMINW) return;                    // no decreasing window at all

    const float xm  = 0.5f * (float)(lenL - 1);
    const float den = (float)lenL * (float)(lenL * lenL - 1) / 12.0f;

    for (int t = tid; t < NF; t += 128) {
        int w = t >> 5, r = t & 31;
        unsigned int bits = (W[w] >> r) | (r ? (W[w + 1] << (32 - r)) : 0u);
        unsigned int nb = ~bits;
        int c = nb ? (__ffs(nb) - 1) : 32;
        if (t + lenL <= NF && c >= lenL - 1) {
            // EDC: reverse cumsum in same order as reference, then dB
            float acc = 0.0f;
            float db[LMAXW];
            for (int j = lenL - 1; j >= 0; j--) {
                acc += sy[t + j];
                db[j] = 10.0f * log10f(fmaxf(acc, 1e-10f));
            }
            float d0 = db[0];
            if (db[lenL - 1] - d0 < -10.0f) {    // selected
                float num = 0.0f;
                for (int j = 1; j < lenL; j++)
                    num += ((float)j - xm) * (db[j] - d0);
                float slope = num / den;         // slope <= 0 here
                float rt60  = (-60.0f / slope) * 0.0375f;  // HOP/FS
                unsigned int u = __float_as_uint(rt60);
                unsigned int key = (u & 0x80000000u) ? ~u : (u | 0x80000000u);
                int pos = atomicAdd(&scnt, 1);   // smem atomic (cheap)
                skey[pos] = key;
            }
        }
    }
    __syncthreads();

    const int cnt = scnt;
    if (cnt == 0) return;
    if (tid == 0) sbase = atomicAdd(&g_nvalid[b], cnt);  // ONE global atomic
    __syncthreads();
    unsigned int* dst = g_keys + (size_t)b * FT + sbase;
    for (int i = tid; i < cnt; i += 128) dst[i] = skey[i];
}

// ---------------- median: one block per batch, 4-pass radix select ----------
__global__ __launch_bounds__(512) void median_kernel(const float* __restrict__ coeffs,
                                                     float* __restrict__ out) {
    const int b   = blockIdx.x;
    const int tid = threadIdx.x;
    __shared__ unsigned int skeys[SMEMK];
    __shared__ int          hist[256];
    __shared__ unsigned int s_pfx;
    __shared__ int          s_k;

    const int n = g_nvalid[b];
    if (n == 0) {
        if (tid == 0) out[b] = 0.5f;             // DEFAULT_RT60 (>= 0.01)
        return;
    }
    const unsigned int* gk = g_keys + (size_t)b * FT;
    const bool fits = (n <= SMEMK);
    if (fits)
        for (int i = tid; i < n; i += 512) skeys[i] = gk[i];
    if (tid == 0) { s_pfx = 0u; s_k = (n - 1) >> 1; }
    __syncthreads();

    #pragma unroll
    for (int pass = 0; pass < 4; pass++) {
        for (int i = tid; i < 256; i += 512) hist[i] = 0;
        __syncthreads();
        const int shift = 24 - 8 * pass;
        const unsigned int pfx   = s_pfx;
        const unsigned int hmask = (pass == 0) ? 0u : (0xFFFFFFFFu << (shift + 8));
        if (fits) {
            for (int i = tid; i < n; i += 512) {
                unsigned int key = skeys[i];
                if ((key & hmask) == pfx) atomicAdd(&hist[(key >> shift) & 255], 1);
            }
        } else {
            for (int i = tid; i < n; i += 512) {
                unsigned int key = gk[i];
                if ((key & hmask) == pfx) atomicAdd(&hist[(key >> shift) & 255], 1);
            }
        }
        __syncthreads();

        if (tid < 32) {                          // warp-scan bin select
            const int lane = tid;
            const int base = lane * 8;
            int c[8]; int s = 0;
            #pragma unroll
            for (int q = 0; q < 8; q++) { c[q] = hist[base + q]; s += c[q]; }
            int excl = s;
            #pragma unroll
            for (int off = 1; off < 32; off <<= 1) {
                int nn = __shfl_up_sync(0xFFFFFFFFu, excl, off);
                if (lane >= off) excl += nn;
            }
            excl -= s;                           // exclusive prefix across lanes
            const int k0 = s_k;
            int bin = 256, cumAt = 0, cum = excl;
            #pragma unroll
            for (int q = 0; q < 8; q++) {
                if (bin == 256 && cum + c[q] > k0) { bin = base + q; cumAt = cum; }
                cum += c[q];
            }
            unsigned int ball = __ballot_sync(0xFFFFFFFFu, bin < 256);
            int src = __ffs(ball) - 1;           // guaranteed: total >= k0+1
            if (lane == src) {
                s_k   = k0 - cumAt;
                s_pfx = pfx | ((unsigned int)bin << shift);
            }
        }
        __syncthreads();
    }

    if (tid == 0) {
        unsigned int key = s_pfx;
        unsigned int u = (key & 0x80000000u) ? (key ^ 0x80000000u) : ~key;
        float med = __uint_as_float(u);
        out[b] = fmaxf(coeffs[0] + coeffs[1] * med, 0.01f);
    }
}

// ---------------- launcher ---------------------------------------------------
extern "C" void kernel_launch(void* const* d_in, const int* in_sizes, int n_in,
                              void* d_out, int out_size) {
    const float* y      = (const float*)d_in[0];
    const float* coeffs = (const float*)d_in[1];
    float*       out    = (float*)d_out;

    stft_kernel<<<NB * NFQ, 256>>>(y);
    rt60_kernel<<<NB * NBINS, 128>>>();
    median_kernel<<<NB, 512>>>(coeffs, out);
}

// round 13
// speedup vs baseline: 1.8890x; 1.0499x over previous
#include <cuda_runtime.h>
#include <math.h>

// ---------------- problem constants (fixed shapes from setup_inputs) -------
#define NB      32          // batch
#define TSAMP   160000      // samples per batch
#define KFFT    1024        // n_fft
#define MWIN    800         // win_length
#define HOP     600
#define NBINS   256
#define NF      267         // 1 + (160000+1024-1024)/600
#define NFP     134         // frame pairs (two real frames per complex FFT)
#define LMAXW   13
#define LMINW   3
#define FT      (NBINS*NF)  // 68352 (worst-case valid keys per batch)
#define SMEMK   8192        // median smem key cache capacity

#define PHI1(a) ((a) + 4 * ((a) >> 4))   // skew for stage1->stage2 buffer
#define TWI(i)  ((i) + ((i) >> 4))       // skewed twiddle index (CF strided reads)

__device__ __forceinline__ float2 cmul(float2 a, float2 b) {
    return make_float2(a.x * b.x - a.y * b.y, a.x * b.y + a.y * b.x);
}

// ---------------- scratch (__device__ globals, no allocation) --------------
__device__ float        g_Yt[NB*NF*NBINS];      // [B, T, F]: stft-coalesced
__device__ unsigned int g_keys[NB*FT];          // compacted valid keys
__device__ int          g_nvalid[NB];

// ---------------- STFT power: one block per (batch, frame-pair) ------------
// Two real frames packed as re/im of one complex 1024-pt FFT (radix-4
// Stockham autosort). Input register-resident through stage 0; float2
// interleaved smem; 1 twiddle load per stage; trimmed final stage;
// Hermitian unpack; fully coalesced [B,T,F] output stores.
__global__ __launch_bounds__(256) void stft_kernel(const float* __restrict__ y) {
    const int p  = blockIdx.x % NFP;
    const int b  = blockIdx.x / NFP;
    const int fa = 2 * p;
    const int fb = 2 * p + 1;                    // may be NF (dropped)
    __shared__ __align__(16) float2 A[1280];
    __shared__ __align__(16) float2 B[1024];
    __shared__ float2 stw[272];
    const int tid = threadIdx.x;

    if (p == 0 && tid == 0) g_nvalid[b] = 0;     // replay-state reset

    {   // twiddle table: exp(-2*pi*i*k/1024), k<256, skew-stored
        float s, c;
        sincospif(-(float)tid / 512.0f, &s, &c);
        stw[TWI(tid)] = make_float2(c, s);
    }

    // windowed input, elements tid+256q held in registers (natural order)
    const float* yb = y + (size_t)b * TSAMP;
    float2 v[4];
    #pragma unroll
    for (int q = 0; q < 4; q++) {
        int j = tid + q * 256;
        float va = 0.0f, vb = 0.0f;
        if (j >= 112 && j < 912) {               // zero-padded centered window
            float w = 0.5f - 0.5f * cospif((float)(j - 112) / 400.0f);
            int sa = fa * HOP + j - 512;         // center=True: pad K/2 = 512
            if (sa < 0) sa = -sa;
            else if (sa >= TSAMP) sa = 2 * (TSAMP - 1) - sa;
            va = __ldg(yb + sa) * w;
            if (fb < NF) {
                int sb = fb * HOP + j - 512;
                if (sb < 0) sb = -sb;
                else if (sb >= TSAMP) sb = 2 * (TSAMP - 1) - sb;
                vb = __ldg(yb + sb) * w;
            }
        }
        v[q] = make_float2(va, vb);
    }

    // stage 0 (Ns=1, twiddles = 1): registers -> B, contiguous STS.128 x2
    {
        float2 t0 = {v[0].x + v[2].x, v[0].y + v[2].y};
        float2 t1 = {v[0].x - v[2].x, v[0].y - v[2].y};
        float2 t2 = {v[1].x + v[3].x, v[1].y + v[3].y};
        float2 t3 = {v[1].x - v[3].x, v[1].y - v[3].y};
        ((float4*)B)[2 * tid]     = make_float4(t0.x + t2.x, t0.y + t2.y,
                                                t1.x + t3.y, t1.y - t3.x);
        ((float4*)B)[2 * tid + 1] = make_float4(t0.x - t2.x, t0.y - t2.y,
                                                t1.x - t3.y, t1.y + t3.x);
    }
    __syncthreads();                             // covers B and stw

    #define BFLY(w1, v0, v1, v2, v3, o0, o1, o2, o3)                          \
        {                                                                     \
            float2 w2 = cmul(w1, w1), w3 = cmul(w1, w2);                      \
            float2 a1 = cmul(w1, v1), a2 = cmul(w2, v2), a3 = cmul(w3, v3);   \
            float2 t0 = {v0.x + a2.x, v0.y + a2.y};                           \
            float2 t1 = {v0.x - a2.x, v0.y - a2.y};                           \
            float2 t2 = {a1.x + a3.x, a1.y + a3.y};                           \
            float2 t3 = {a1.x - a3.x, a1.y - a3.y};                           \
            o0 = make_float2(t0.x + t2.x, t0.y + t2.y);                       \
            o1 = make_float2(t1.x + t3.y, t1.y - t3.x);                       \
            o2 = make_float2(t0.x - t2.x, t0.y - t2.y);                       \
            o3 = make_float2(t1.x - t3.y, t1.y + t3.x);                       \
        }

    // stage 1 (Ns=4): B -> A (PHI1 layout)
    {
        const int m = tid & 3;
        float2 v0 = B[tid], v1 = B[tid + 256], v2 = B[tid + 512], v3 = B[tid + 768];
        float2 w1 = stw[TWI(m * 64)];
        float2 o0, o1, o2, o3;
        BFLY(w1, v0, v1, v2, v3, o0, o1, o2, o3);
        const int base = ((tid >> 2) << 4) + m;
        A[PHI1(base)]      = o0; A[PHI1(base + 4)]  = o1;
        A[PHI1(base + 8)]  = o2; A[PHI1(base + 12)] = o3;
    }
    __syncthreads();

    // stage 2 (Ns=16): A (PHI1) -> B (identity)
    {
        const int m = tid & 15;
        float2 v0 = A[PHI1(tid)],       v1 = A[PHI1(tid + 256)];
        float2 v2 = A[PHI1(tid + 512)], v3 = A[PHI1(tid + 768)];
        float2 w1 = stw[TWI(m * 16)];
        float2 o0, o1, o2, o3;
        BFLY(w1, v0, v1, v2, v3, o0, o1, o2, o3);
        const int base = ((tid >> 4) << 6) + m;
        B[base]      = o0; B[base + 16] = o1;
        B[base + 32] = o2; B[base + 48] = o3;
    }
    __syncthreads();

    // stage 3 (Ns=64): B -> A (identity)
    {
        const int m = tid & 63;
        float2 v0 = B[tid], v1 = B[tid + 256], v2 = B[tid + 512], v3 = B[tid + 768];
        float2 w1 = stw[TWI(m * 4)];
        float2 o0, o1, o2, o3;
        BFLY(w1, v0, v1, v2, v3, o0, o1, o2, o3);
        const int base = ((tid >> 6) << 8) + m;
        A[base]       = o0; A[base + 64]  = o1;
        A[base + 128] = o2; A[base + 192] = o3;
    }
    __syncthreads();

    // stage 4 (Ns=256, trimmed): Z[tid] stays in regs; only Z[tid+768] -> smem
    float2 zk;
    {
        float2 v0 = A[tid], v1 = A[tid + 256], v2 = A[tid + 512], v3 = A[tid + 768];
        float2 w1 = stw[TWI(tid)];
        float2 w2 = cmul(w1, w1), w3 = cmul(w1, w2);
        float2 a1 = cmul(w1, v1), a2 = cmul(w2, v2), a3 = cmul(w3, v3);
        float2 t0 = {v0.x + a2.x, v0.y + a2.y};
        float2 t1 = {v0.x - a2.x, v0.y - a2.y};
        float2 t2 = {a1.x + a3.x, a1.y + a3.y};
        float2 t3 = {a1.x - a3.x, a1.y - a3.y};
        zk = make_float2(t0.x + t2.x, t0.y + t2.y);          // Z[tid]
        B[768 + tid] = make_float2(t1.x - t3.y, t1.y + t3.x); // Z[tid+768]
    }
    __syncthreads();

    // Hermitian unpack; power, layout [B, T, F] -> coalesced 256-bin stores
    float2 zc = (tid == 0) ? zk : B[1024 - tid];  // Z[K - tid]
    float xar = 0.5f * (zk.x + zc.x), xai = 0.5f * (zk.y - zc.y);
    float ddr = zk.x - zc.x,          ddi = zk.y + zc.y;
    float xbr = 0.5f * ddi,           xbi = -0.5f * ddr;
    g_Yt[((size_t)b * NF + fa) * NBINS + tid] = xar * xar + xai * xai;
    if (fb < NF)
        g_Yt[((size_t)b * NF + fb) * NBINS + tid] = xbr * xbr + xbi * xbi;
}

// ---------------- RT60 per (batch, subband): compact valid keys -------------
// Reads g_Yt strided (stride NBINS); sectors shared across 8 adjacent blocks
// via L2. Memory pipes here are nearly idle, so the sector cost hides.
__global__ __launch_bounds__(128) void rt60_kernel() {
    const int f = blockIdx.x % NBINS;
    const int b = blockIdx.x / NBINS;
    __shared__ float        sy[NF];
    __shared__ unsigned int W[12];               // decrease-flag bitmask (267 bits)
    __shared__ unsigned int skey[NF];
    __shared__ int          sbest;
    __shared__ int          scnt;
    __shared__ int          sbase;
    const int tid  = threadIdx.x;
    const int lane = tid & 31;
    if (tid < 12) W[tid] = 0u;
    if (tid == 0) { sbest = 0; scnt = 0; }

    const float* col = g_Yt + (size_t)b * NF * NBINS + f;
    for (int t = tid; t < NF; t += 128) sy[t] = __ldg(col + (size_t)t * NBINS);
    __syncthreads();

    // pack strict-decrease flags into bitmask words via ballot
    #pragma unroll
    for (int base = 0; base < 288; base += 128) {
        int t = base + tid;
        bool flag = (t + 1 < NF) && (sy[t + 1] < sy[t]);
        unsigned int m = __ballot_sync(0xFFFFFFFFu, flag);
        if (lane == 0 && (t >> 5) < 9) W[t >> 5] = m;
    }
    __syncthreads();

    // best window length: run length from t = ffs of first zero bit
    int localbest = 0;
    for (int t = tid; t < NF; t += 128) {
        int w = t >> 5, r = t & 31;
        unsigned int bits = (W[w] >> r) | (r ? (W[w + 1] << (32 - r)) : 0u);
        unsigned int nb = ~bits;
        int c = nb ? (__ffs(nb) - 1) : 32;
        if (c > LMAXW - 1) c = LMAXW - 1;
        int cand = c + 1;
        int rem  = NF - t;
        if (cand > rem) cand = rem;
        if (cand > localbest) localbest = cand;
    }
    atomicMax(&sbest, localbest);
    __syncthreads();

    const int lenL = sbest;
    if (lenL < LMINW) return;                    // no decreasing window at all

    const float xm  = 0.5f * (float)(lenL - 1);
    const float den = (float)lenL * (float)(lenL * lenL - 1) / 12.0f;

    for (int t = tid; t < NF; t += 128) {
        int w = t >> 5, r = t & 31;
        unsigned int bits = (W[w] >> r) | (r ? (W[w + 1] << (32 - r)) : 0u);
        unsigned int nb = ~bits;
        int c = nb ? (__ffs(nb) - 1) : 32;
        if (t + lenL <= NF && c >= lenL - 1) {
            // EDC: reverse cumsum in same order as reference, then dB
            float acc = 0.0f;
            float db[LMAXW];
            for (int j = lenL - 1; j >= 0; j--) {
                acc += sy[t + j];
                db[j] = 10.0f * log10f(fmaxf(acc, 1e-10f));
            }
            float d0 = db[0];
            if (db[lenL - 1] - d0 < -10.0f) {    // selected
                float num = 0.0f;
                for (int j = 1; j < lenL; j++)
                    num += ((float)j - xm) * (db[j] - d0);
                float slope = num / den;         // slope <= 0 here
                float rt60  = (-60.0f / slope) * 0.0375f;  // HOP/FS
                unsigned int u = __float_as_uint(rt60);
                unsigned int key = (u & 0x80000000u) ? ~u : (u | 0x80000000u);
                int pos = atomicAdd(&scnt, 1);   // smem atomic (cheap)
                skey[pos] = key;
            }
        }
    }
    __syncthreads();

    const int cnt = scnt;
    if (cnt == 0) return;
    if (tid == 0) sbase = atomicAdd(&g_nvalid[b], cnt);  // ONE global atomic
    __syncthreads();
    unsigned int* dst = g_keys + (size_t)b * FT + sbase;
    for (int i = tid; i < cnt; i += 128) dst[i] = skey[i];
}

// ---------------- median: one block per batch, 4-pass radix select ----------
__global__ __launch_bounds__(512) void median_kernel(const float* __restrict__ coeffs,
                                                     float* __restrict__ out) {
    const int b   = blockIdx.x;
    const int tid = threadIdx.x;
    __shared__ unsigned int skeys[SMEMK];
    __shared__ int          hist[256];
    __shared__ unsigned int s_pfx;
    __shared__ int          s_k;

    const int n = g_nvalid[b];
    if (n == 0) {
        if (tid == 0) out[b] = 0.5f;             // DEFAULT_RT60 (>= 0.01)
        return;
    }
    const unsigned int* gk = g_keys + (size_t)b * FT;
    const bool fits = (n <= SMEMK);
    if (fits)
        for (int i = tid; i < n; i += 512) skeys[i] = gk[i];
    if (tid == 0) { s_pfx = 0u; s_k = (n - 1) >> 1; }
    __syncthreads();

    #pragma unroll
    for (int pass = 0; pass < 4; pass++) {
        for (int i = tid; i < 256; i += 512) hist[i] = 0;
        __syncthreads();
        const int shift = 24 - 8 * pass;
        const unsigned int pfx   = s_pfx;
        const unsigned int hmask = (pass == 0) ? 0u : (0xFFFFFFFFu << (shift + 8));
        if (fits) {
            for (int i = tid; i < n; i += 512) {
                unsigned int key = skeys[i];
                if ((key & hmask) == pfx) atomicAdd(&hist[(key >> shift) & 255], 1);
            }
        } else {
            for (int i = tid; i < n; i += 512) {
                unsigned int key = gk[i];
                if ((key & hmask) == pfx) atomicAdd(&hist[(key >> shift) & 255], 1);
            }
        }
        __syncthreads();

        if (tid < 32) {                          // warp-scan bin select
            const int lane = tid;
            const int base = lane * 8;
            int c[8]; int s = 0;
            #pragma unroll
            for (int q = 0; q < 8; q++) { c[q] = hist[base + q]; s += c[q]; }
            int excl = s;
            #pragma unroll
            for (int off = 1; off < 32; off <<= 1) {
                int nn = __shfl_up_sync(0xFFFFFFFFu, excl, off);
                if (lane >= off) excl += nn;
            }
            excl -= s;                           // exclusive prefix across lanes
            const int k0 = s_k;
            int bin = 256, cumAt = 0, cum = excl;
            #pragma unroll
            for (int q = 0; q < 8; q++) {
                if (bin == 256 && cum + c[q] > k0) { bin = base + q; cumAt = cum; }
                cum += c[q];
            }
            unsigned int ball = __ballot_sync(0xFFFFFFFFu, bin < 256);
            int src = __ffs(ball) - 1;           // guaranteed: total >= k0+1
            if (lane == src) {
                s_k   = k0 - cumAt;
                s_pfx = pfx | ((unsigned int)bin << shift);
            }
        }
        __syncthreads();
    }

    if (tid == 0) {
        unsigned int key = s_pfx;
        unsigned int u = (key & 0x80000000u) ? (key ^ 0x80000000u) : ~key;
        float med = __uint_as_float(u);
        out[b] = fmaxf(coeffs[0] + coeffs[1] * med, 0.01f);
    }
}

// ---------------- launcher ---------------------------------------------------
extern "C" void kernel_launch(void* const* d_in, const int* in_sizes, int n_in,
                              void* d_out, int out_size) {
    const float* y      = (const float*)d_in[0];
    const float* coeffs = (const float*)d_in[1];
    float*       out    = (float*)d_out;

    stft_kernel<<<NB * NFP, 256>>>(y);
    rt60_kernel<<<NB * NBINS, 128>>>();
    median_kernel<<<NB, 512>>>(coeffs, out);
}